// round 2
// baseline (speedup 1.0000x reference)
#include <cuda_runtime.h>

#define NLAB   2047
#define NBATCH 2048
#define NTHR   256

// Compact transition tables, gathered once per launch (deterministic, re-done
// every call). Tup[n] = transitions[parent(n), n, :, :] (message n -> parent)
// Tdn[n] = transitions[n, parent(n), :, :] (message parent -> n)
// Layout of the float4: x=T[cd=0][cs=0], y=T[0][1], z=T[1][0], w=T[1][1]
__device__ float4 g_Tup[2048];
__device__ float4 g_Tdn[2048];

__global__ void prep_kernel(const float* __restrict__ trans) {
    int n = blockIdx.x * blockDim.x + threadIdx.x;
    if (n >= NLAB) return;
    if (n == 0) {
        g_Tup[0] = make_float4(0.f, 0.f, 0.f, 0.f);
        g_Tdn[0] = make_float4(0.f, 0.f, 0.f, 0.f);
        return;
    }
    int p = (n - 1) >> 1;
    // transitions[dst, src, cd, cs]: one (dst,src) pair = 4 contiguous floats
    const float4* t4 = reinterpret_cast<const float4*>(trans);
    g_Tup[n] = t4[(size_t)p * NLAB + n];   // dst=parent, src=n
    g_Tdn[n] = t4[(size_t)n * NLAB + p];   // dst=n, src=parent
}

__device__ __forceinline__ float lse2(float u, float v) {
    float m = fmaxf(u, v);
    float d = fminf(u, v) - m;              // <= 0
    return m + __logf(1.0f + __expf(d));
}

__global__ __launch_bounds__(NTHR) void crf_kernel(const float* __restrict__ em,
                                                   float* __restrict__ out) {
    // 6 * 2048 * 4 B = 49152 B = 48 KB static smem -> 4 CTAs/SM
    __shared__ float e0[NLAB + 1], e1[NLAB + 1];
    __shared__ float a0[NLAB + 1], a1[NLAB + 1];
    __shared__ float b0[NLAB + 1], b1[NLAB + 1];

    const int tid = threadIdx.x;
    const size_t boff = (size_t)blockIdx.x * (2 * NLAB);
    const float* er = em + boff;

    // Load emissions row (coalesced) + zero alphas
    for (int i = tid; i < NLAB; i += NTHR) {
        e0[i] = er[i];
        e1[i] = er[NLAB + i];
        a0[i] = 0.f;
        a1[i] = 0.f;
    }
    if (tid == 0) { b0[0] = 0.f; b1[0] = 0.f; }   // root beta
    __syncthreads();

    // ---- upward sweep (alphas): iterate over PARENT levels, each thread
    //      combines both children -> no write conflicts, deterministic.
    #pragma unroll
    for (int pl = 9; pl >= 0; --pl) {
        const int base = (1 << pl) - 1;
        const int cnt  = 1 << pl;
        for (int i = tid; i < cnt; i += NTHR) {
            const int p = base + i;
            const int l = 2 * p + 1;
            const int r = 2 * p + 2;
            float xl0 = e0[l] + a0[l], xl1 = e1[l] + a1[l];
            float xr0 = e0[r] + a0[r], xr1 = e1[r] + a1[r];
            float4 Tl = g_Tup[l];
            float4 Tr = g_Tup[r];
            a0[p] = lse2(xl0 + Tl.x, xl1 + Tl.y) + lse2(xr0 + Tr.x, xr1 + Tr.y);
            a1[p] = lse2(xl0 + Tl.z, xl1 + Tl.w) + lse2(xr0 + Tr.z, xr1 + Tr.w);
        }
        __syncthreads();
    }

    // ---- downward sweep (betas): root -> leaves
    #pragma unroll
    for (int lvl = 1; lvl <= 10; ++lvl) {
        const int base = (1 << lvl) - 1;
        const int cnt  = 1 << lvl;
        for (int i = tid; i < cnt; i += NTHR) {
            const int n = base + i;
            const int p = (n - 1) >> 1;
            float x0 = e0[p] + b0[p], x1 = e1[p] + b1[p];
            float4 T = g_Tdn[n];
            b0[n] = lse2(x0 + T.x, x1 + T.y);
            b1[n] = lse2(x0 + T.z, x1 + T.w);
        }
        __syncthreads();
    }

    // ---- scores + log-softmax over classes, coalesced store
    float* orow = out + boff;
    for (int i = tid; i < NLAB; i += NTHR) {
        float s0 = e0[i] + a0[i] + b0[i];
        float s1 = e1[i] + a1[i] + b1[i];
        float z = lse2(s0, s1);
        orow[i]        = s0 - z;
        orow[NLAB + i] = s1 - z;
    }
}

extern "C" void kernel_launch(void* const* d_in, const int* in_sizes, int n_in,
                              void* d_out, int out_size) {
    const float* em = (const float*)d_in[0];
    const float* tr = (const float*)d_in[1];
    // robustness: identify emissions by its element count
    if (n_in >= 2 && in_sizes[0] != NBATCH * 2 * NLAB) {
        em = (const float*)d_in[1];
        tr = (const float*)d_in[0];
    }
    prep_kernel<<<(NLAB + NTHR - 1) / NTHR, NTHR>>>(tr);
    crf_kernel<<<NBATCH, NTHR>>>(em, (float*)d_out);
}

// round 3
// speedup vs baseline: 1.1325x; 1.1325x over previous
#include <cuda_runtime.h>

#define NLAB   2047
#define NBATCH 2048
#define NTHR   256

// Compact transition tables, gathered once per launch (deterministic).
// Tup[n] = transitions[parent(n), n, :, :]  (message n -> parent)
// Tdn[n] = transitions[n, parent(n), :, :]  (message parent -> n)
// float4: x=T[cd=0][cs=0], y=T[0][1], z=T[1][0], w=T[1][1]
__device__ float4 g_Tup[2048];
__device__ float4 g_Tdn[2048];

__global__ void prep_kernel(const float* __restrict__ trans) {
    int n = blockIdx.x * blockDim.x + threadIdx.x;
    if (n >= NLAB) return;
    if (n == 0) {
        g_Tup[0] = make_float4(0.f, 0.f, 0.f, 0.f);
        g_Tdn[0] = make_float4(0.f, 0.f, 0.f, 0.f);
        return;
    }
    int p = (n - 1) >> 1;
    const float4* t4 = reinterpret_cast<const float4*>(trans);
    g_Tup[n] = t4[(size_t)p * NLAB + n];   // dst=parent, src=n
    g_Tdn[n] = t4[(size_t)n * NLAB + p];   // dst=n, src=parent
}

__device__ __forceinline__ float lse2(float u, float v) {
    float m = fmaxf(u, v);
    float d = fminf(u, v) - m;              // <= 0
    return m + __logf(1.0f + __expf(d));
}

// smem: E (becomes t = e + beta in place during the down sweep) and A (alphas).
// 4 * 2048 * 4 B = 32 KB -> ~6 CTAs/SM.
__global__ __launch_bounds__(NTHR) void crf_kernel(const float* __restrict__ em,
                                                   float* __restrict__ out) {
    __shared__ float E0[NLAB + 1], E1[NLAB + 1];
    __shared__ float A0[NLAB + 1], A1[NLAB + 1];

    const int tid = threadIdx.x;
    const size_t boff = (size_t)blockIdx.x * (2 * NLAB);
    const float* er = em + boff;
    float* orow = out + boff;

    // Load emissions row (coalesced) + zero alphas
    for (int i = tid; i < NLAB; i += NTHR) {
        E0[i] = er[i];
        E1[i] = er[NLAB + i];
        A0[i] = 0.f;
        A1[i] = 0.f;
    }
    __syncthreads();

    // ---- upward sweep (alphas): iterate over PARENT levels, each thread
    //      combines both children -> no write conflicts, deterministic.
    #pragma unroll
    for (int pl = 9; pl >= 0; --pl) {
        const int base = (1 << pl) - 1;
        const int cnt  = 1 << pl;
        for (int i = tid; i < cnt; i += NTHR) {
            const int p = base + i;
            const int l = 2 * p + 1;
            const int r = 2 * p + 2;
            float xl0 = E0[l] + A0[l], xl1 = E1[l] + A1[l];
            float xr0 = E0[r] + A0[r], xr1 = E1[r] + A1[r];
            float4 Tl = g_Tup[l];
            float4 Tr = g_Tup[r];
            A0[p] = lse2(xl0 + Tl.x, xl1 + Tl.y) + lse2(xr0 + Tr.x, xr1 + Tr.y);
            A1[p] = lse2(xl0 + Tl.z, xl1 + Tl.w) + lse2(xr0 + Tr.z, xr1 + Tr.w);
        }
        __syncthreads();
    }

    // ---- root output: t[0] = e[0] (beta=0), score = t + alpha
    if (tid == 0) {
        float s0 = E0[0] + A0[0];
        float s1 = E1[0] + A1[0];
        float z = lse2(s0, s1);
        orow[0]        = s0 - z;
        orow[NLAB + 0] = s1 - z;
    }
    // no barrier needed: level-1 reads E[0] (unchanged) and A written above barrier

    // ---- downward sweep: transform E in place to t = e + beta, and emit
    //      the normalized score as soon as t[n] is ready.
    #pragma unroll
    for (int lvl = 1; lvl <= 10; ++lvl) {
        const int base = (1 << lvl) - 1;
        const int cnt  = 1 << lvl;
        for (int i = tid; i < cnt; i += NTHR) {
            const int n = base + i;
            const int p = (n - 1) >> 1;
            float tp0 = E0[p], tp1 = E1[p];          // parent t = e + beta (final)
            float4 T = g_Tdn[n];
            float t0 = E0[n] + lse2(tp0 + T.x, tp1 + T.y);
            float t1 = E1[n] + lse2(tp0 + T.z, tp1 + T.w);
            E0[n] = t0;
            E1[n] = t1;
            float s0 = t0 + A0[n];
            float s1 = t1 + A1[n];
            float z = lse2(s0, s1);
            orow[n]        = s0 - z;
            orow[NLAB + n] = s1 - z;
        }
        if (lvl < 10) __syncthreads();   // children of last level don't exist
    }
}

extern "C" void kernel_launch(void* const* d_in, const int* in_sizes, int n_in,
                              void* d_out, int out_size) {
    const float* em = (const float*)d_in[0];
    const float* tr = (const float*)d_in[1];
    if (n_in >= 2 && in_sizes[0] != NBATCH * 2 * NLAB) {
        em = (const float*)d_in[1];
        tr = (const float*)d_in[0];
    }
    prep_kernel<<<(NLAB + NTHR - 1) / NTHR, NTHR>>>(tr);
    crf_kernel<<<NBATCH, NTHR>>>(em, (float*)d_out);
}